// round 1
// baseline (speedup 1.0000x reference)
#include <cuda_runtime.h>
#include <cstdint>

#define NROWS  512
#define INSIZE 512
#define KK     64
#define DD     16
#define MM     (KK * DD)        // 1024
#define OUTW   (INSIZE + KK)    // 576

// Scratch for feat = x @ W^T + b  (512 x 1024 fp32 = 2MB)
__device__ float g_feat[NROWS * MM];

// ---------------------------------------------------------------------------
// Packed f32x2 helpers (sm_103a FFMA2/FADD2 path)
// ---------------------------------------------------------------------------
__device__ __forceinline__ unsigned long long addf32x2(unsigned long long a,
                                                       unsigned long long b) {
    unsigned long long r;
    asm("add.rn.f32x2 %0, %1, %2;" : "=l"(r) : "l"(a), "l"(b));
    return r;
}

__device__ __forceinline__ unsigned long long pk2(float lo, float hi) {
    unsigned long long r;
    asm("mov.b64 %0, {%1, %2};" : "=l"(r)
        : "r"(__float_as_uint(lo)), "r"(__float_as_uint(hi)));
    return r;
}

__device__ __forceinline__ float lo32(unsigned long long v) {
    return __uint_as_float((unsigned int)v);
}
__device__ __forceinline__ float hi32(unsigned long long v) {
    return __uint_as_float((unsigned int)(v >> 32));
}

// ---------------------------------------------------------------------------
// Kernel 1: feat = x @ W^T + b
// x: [512,512], W: [1024,512], b: [1024]  -> g_feat [512,1024]
// 64x64 output tile per block, BK=16, 256 threads, 4x4 micro-tile.
// ---------------------------------------------------------------------------
__global__ __launch_bounds__(256)
void gemm_kernel(const float* __restrict__ x, const float* __restrict__ W,
                 const float* __restrict__ b) {
    __shared__ float Xs[16][64];   // [k][n-row]  (transposed on store)
    __shared__ float Ws[16][64];   // [k][m-col]

    const int block_m = blockIdx.x * 64;   // output col (W row)
    const int block_n = blockIdx.y * 64;   // output row (x row)
    const int tid = threadIdx.x;

    const int lr = tid >> 2;          // 0..63
    const int lc = (tid & 3) * 4;     // 0,4,8,12

    const int tx = tid & 15;          // n-dir 0..15
    const int ty = tid >> 4;          // m-dir 0..15

    float acc[4][4];
#pragma unroll
    for (int a = 0; a < 4; a++)
#pragma unroll
        for (int c = 0; c < 4; c++) acc[a][c] = 0.f;

    for (int k0 = 0; k0 < INSIZE; k0 += 16) {
        float4 xv = *(const float4*)&x[(block_n + lr) * INSIZE + k0 + lc];
        float4 wv = *(const float4*)&W[(block_m + lr) * INSIZE + k0 + lc];
        Xs[lc + 0][lr] = xv.x; Xs[lc + 1][lr] = xv.y;
        Xs[lc + 2][lr] = xv.z; Xs[lc + 3][lr] = xv.w;
        Ws[lc + 0][lr] = wv.x; Ws[lc + 1][lr] = wv.y;
        Ws[lc + 2][lr] = wv.z; Ws[lc + 3][lr] = wv.w;
        __syncthreads();

#pragma unroll
        for (int kk = 0; kk < 16; kk++) {
            float4 xr = *(const float4*)&Xs[kk][tx * 4];
            float4 wr = *(const float4*)&Ws[kk][ty * 4];
            float xa[4] = {xr.x, xr.y, xr.z, xr.w};
            float wb[4] = {wr.x, wr.y, wr.z, wr.w};
#pragma unroll
            for (int a = 0; a < 4; a++)
#pragma unroll
                for (int c = 0; c < 4; c++) acc[a][c] += xa[a] * wb[c];
        }
        __syncthreads();
    }

    float4 bv = *(const float4*)&b[block_m + ty * 4];
    float bb[4] = {bv.x, bv.y, bv.z, bv.w};
#pragma unroll
    for (int a = 0; a < 4; a++) {
        float4 o;
        o.x = acc[a][0] + bb[0];
        o.y = acc[a][1] + bb[1];
        o.z = acc[a][2] + bb[2];
        o.w = acc[a][3] + bb[3];
        *(float4*)&g_feat[(block_n + tx * 4 + a) * MM + block_m + ty * 4] = o;
    }
}

// ---------------------------------------------------------------------------
// Kernel 2: pairwise L1 + exp reduction.
// blockIdx.x = k (0..63), blockIdx.y = i-tile (0..3), 128 threads, 1 i/thread.
// Shared holds NEGATED feat[:, k, :] packed as f32x2 so the diff is a single
// packed add; |.| via two 32-bit LOP3 (alu pipe) to balance fma/alu pipes.
// ---------------------------------------------------------------------------
__global__ __launch_bounds__(128)
void pairwise_kernel(float* __restrict__ out) {
    __shared__ __align__(16) unsigned long long sNeg[NROWS * 8];  // 32 KB

    const int k   = blockIdx.x;
    const int i0  = blockIdx.y * 128;
    const int tid = threadIdx.x;

    // Fill shared with -feat[j, k*16 .. k*16+15], packed into 8 f32x2 per row.
    // 512 rows * 4 float4 = 2048 float4 loads over 128 threads.
    for (int idx = tid; idx < NROWS * 4; idx += 128) {
        int j = idx >> 2;
        int c = (idx & 3) * 4;
        float4 v = *(const float4*)&g_feat[j * MM + k * DD + c];
        sNeg[j * 8 + (c >> 1) + 0] = pk2(-v.x, -v.y);
        sNeg[j * 8 + (c >> 1) + 1] = pk2(-v.z, -v.w);
    }
    __syncthreads();

    const int i = i0 + tid;

    // Own feature row (positive), packed.
    unsigned long long fi[8];
    {
        const float4* p = (const float4*)&g_feat[i * MM + k * DD];
#pragma unroll
        for (int q = 0; q < 4; q++) {
            float4 v = p[q];
            fi[q * 2 + 0] = pk2(v.x, v.y);
            fi[q * 2 + 1] = pk2(v.z, v.w);
        }
    }

    const unsigned long long ABSM = 0x7fffffff7fffffffULL;
    float total = 0.f;

#pragma unroll 2
    for (int j = 0; j < NROWS; j++) {
        const ulonglong2* row = (const ulonglong2*)&sNeg[j * 8];
        ulonglong2 q0 = row[0], q1 = row[1], q2 = row[2], q3 = row[3];
        unsigned long long fj[8] = {q0.x, q0.y, q1.x, q1.y,
                                    q2.x, q2.y, q3.x, q3.y};
        unsigned long long acc = 0ULL;  // packed (0,0)
#pragma unroll
        for (int p = 0; p < 8; p++) {
            unsigned long long d = addf32x2(fi[p], fj[p]);  // fi - feat_j
            d &= ABSM;                                      // |.| (2x LOP3)
            acc = addf32x2(acc, d);
        }
        float norm = lo32(acc) + hi32(acc);
        float e = __expf(-norm);
        total += (j == i) ? 0.f : e;   // diagonal erased
    }

    out[i * OUTW + INSIZE + k] = total;
}

// ---------------------------------------------------------------------------
// Kernel 3: copy x into out[:, 0:512]  (row stride 576 floats = 144 float4)
// ---------------------------------------------------------------------------
__global__ __launch_bounds__(256)
void copyx_kernel(const float* __restrict__ x, float* __restrict__ out) {
    int idx = blockIdx.x * blockDim.x + threadIdx.x;  // over 512*128 float4
    int r = idx >> 7;         // /128
    int c = idx & 127;
    ((float4*)out)[r * 144 + c] = ((const float4*)x)[idx];
}

// ---------------------------------------------------------------------------
extern "C" void kernel_launch(void* const* d_in, const int* in_sizes, int n_in,
                              void* d_out, int out_size) {
    const float* x = (const float*)d_in[0];   // [512,512]
    const float* W = (const float*)d_in[1];   // [1024,512]
    const float* b = (const float*)d_in[2];   // [1024]
    float* out = (float*)d_out;               // [512,576]

    dim3 ggrid(MM / 64, NROWS / 64);          // (16, 8)
    gemm_kernel<<<ggrid, 256>>>(x, W, b);

    dim3 pgrid(KK, NROWS / 128);              // (64, 4)
    pairwise_kernel<<<pgrid, 128>>>(out);

    copyx_kernel<<<(NROWS * 128) / 256, 256>>>(x, out);
}

// round 2
// speedup vs baseline: 1.0311x; 1.0311x over previous
#include <cuda_runtime.h>
#include <cstdint>

#define NROWS  512
#define INSIZE 512
#define KK     64
#define DD     16
#define MM     (KK * DD)        // 1024
#define OUTW   (INSIZE + KK)    // 576
#define BK     16

// Scratch for feat = x @ W^T + b  (512 x 1024 fp32 = 2MB)
__device__ float g_feat[NROWS * MM];

// ---------------------------------------------------------------------------
// Packed f32x2 helpers
// ---------------------------------------------------------------------------
__device__ __forceinline__ unsigned long long addf32x2(unsigned long long a,
                                                       unsigned long long b) {
    unsigned long long r;
    asm("add.rn.f32x2 %0, %1, %2;" : "=l"(r) : "l"(a), "l"(b));
    return r;
}
__device__ __forceinline__ unsigned long long fmaf32x2(unsigned long long a,
                                                       unsigned long long b,
                                                       unsigned long long c) {
    unsigned long long r;
    asm("fma.rn.f32x2 %0, %1, %2, %3;" : "=l"(r) : "l"(a), "l"(b), "l"(c));
    return r;
}
__device__ __forceinline__ unsigned long long pk2(float lo, float hi) {
    unsigned long long r;
    asm("mov.b64 %0, {%1, %2};" : "=l"(r)
        : "r"(__float_as_uint(lo)), "r"(__float_as_uint(hi)));
    return r;
}
__device__ __forceinline__ float lo32(unsigned long long v) {
    return __uint_as_float((unsigned int)v);
}
__device__ __forceinline__ float hi32(unsigned long long v) {
    return __uint_as_float((unsigned int)(v >> 32));
}

// ---------------------------------------------------------------------------
// Kernel 1: feat = x @ W^T + b   via packed FFMA2.
// 64x64 tile, 256 threads, thread-tile 4 rows x 4 cols (2 packed col-pairs).
// x-tile stored DUPLICATED in smem so LDS.128 yields (x_r,x_r),(x_{r+1},x_{r+1})
// without MOV-packing. Double-buffered, 1 sync per BK step.
// ---------------------------------------------------------------------------
__global__ __launch_bounds__(256)
void gemm_kernel(const float* __restrict__ x, const float* __restrict__ W,
                 const float* __restrict__ b) {
    __shared__ __align__(16) float XsD[2][BK][128];  // [buf][k][2*row] duplicated
    __shared__ __align__(16) float Ws [2][BK][64];   // [buf][k][col]

    const int bm = blockIdx.x * 64;   // feat col tile (W rows)
    const int bn = blockIdx.y * 64;   // feat row tile (x rows)
    const int tid = threadIdx.x;

    // load mapping: 64 rows x 16 k per tile, float4 along k
    const int lr = tid >> 2;          // 0..63
    const int lc = (tid & 3) * 4;     // 0,4,8,12

    // compute mapping
    const int tx = tid & 15;          // col group: cols 4*tx..4*tx+3
    const int ty = tid >> 4;          // row group: rows 4*ty..4*ty+3

    const float* xg = &x[(bn + lr) * INSIZE + lc];
    const float* wg = &W[(bm + lr) * INSIZE + lc];

    unsigned long long acc[4][2];
#pragma unroll
    for (int r = 0; r < 4; r++) { acc[r][0] = 0ULL; acc[r][1] = 0ULL; }

    // prologue: load + store tile 0
    float4 xv = *(const float4*)xg;
    float4 wv = *(const float4*)wg;
    int buf = 0;
    {
        float xa[4] = {xv.x, xv.y, xv.z, xv.w};
        float wa[4] = {wv.x, wv.y, wv.z, wv.w};
#pragma unroll
        for (int q = 0; q < 4; q++) {
            XsD[buf][lc + q][2 * lr]     = xa[q];
            XsD[buf][lc + q][2 * lr + 1] = xa[q];
            Ws [buf][lc + q][lr]         = wa[q];
        }
    }
    __syncthreads();

    for (int k0 = BK; k0 <= INSIZE; k0 += BK) {
        const bool more = (k0 < INSIZE);
        float4 xv2, wv2;
        if (more) {
            xv2 = *(const float4*)(xg + k0);
            wv2 = *(const float4*)(wg + k0);
        }

#pragma unroll
        for (int kk = 0; kk < BK; kk++) {
            ulonglong2 xp = *(const ulonglong2*)&XsD[buf][kk][8 * ty];      // rows 4ty,4ty+1 dup
            ulonglong2 xq = *(const ulonglong2*)&XsD[buf][kk][8 * ty + 4];  // rows 4ty+2,4ty+3 dup
            ulonglong2 wp = *(const ulonglong2*)&Ws [buf][kk][4 * tx];      // col pairs
            acc[0][0] = fmaf32x2(xp.x, wp.x, acc[0][0]);
            acc[0][1] = fmaf32x2(xp.x, wp.y, acc[0][1]);
            acc[1][0] = fmaf32x2(xp.y, wp.x, acc[1][0]);
            acc[1][1] = fmaf32x2(xp.y, wp.y, acc[1][1]);
            acc[2][0] = fmaf32x2(xq.x, wp.x, acc[2][0]);
            acc[2][1] = fmaf32x2(xq.x, wp.y, acc[2][1]);
            acc[3][0] = fmaf32x2(xq.y, wp.x, acc[3][0]);
            acc[3][1] = fmaf32x2(xq.y, wp.y, acc[3][1]);
        }

        if (more) {
            buf ^= 1;
            float xa[4] = {xv2.x, xv2.y, xv2.z, xv2.w};
            float wa[4] = {wv2.x, wv2.y, wv2.z, wv2.w};
#pragma unroll
            for (int q = 0; q < 4; q++) {
                XsD[buf][lc + q][2 * lr]     = xa[q];
                XsD[buf][lc + q][2 * lr + 1] = xa[q];
                Ws [buf][lc + q][lr]         = wa[q];
            }
            __syncthreads();
        }
    }

    // epilogue: add bias, store
    float4 bv = *(const float4*)&b[bm + 4 * tx];
#pragma unroll
    for (int r = 0; r < 4; r++) {
        float4 o;
        o.x = lo32(acc[r][0]) + bv.x;
        o.y = hi32(acc[r][0]) + bv.y;
        o.z = lo32(acc[r][1]) + bv.z;
        o.w = hi32(acc[r][1]) + bv.w;
        *(float4*)&g_feat[(bn + 4 * ty + r) * MM + bm + 4 * tx] = o;
    }
}

// ---------------------------------------------------------------------------
// Kernel 2: pairwise L1 + exp reduction, fused with the x -> out copy.
// blockIdx.x = k (0..63), blockIdx.y = i-tile (0..1), 256 threads, 1 i/thread.
// Grid = 128 blocks = exactly one wave on 148 SMs.
// ---------------------------------------------------------------------------
__global__ __launch_bounds__(256)
void pairwise_kernel(const float* __restrict__ x, float* __restrict__ out) {
    __shared__ __align__(16) unsigned long long sNeg[NROWS * 8];  // 32 KB

    const int k   = blockIdx.x;
    const int i0  = blockIdx.y * 256;
    const int tid = threadIdx.x;

    // Fused copy: x -> out[:, 0:512]. 64K float4 over 128 blocks x 256 threads.
    {
        const int id = blockIdx.x + (blockIdx.y << 6);   // 0..127
        const float4* xin = (const float4*)x;
        float4* o4 = (float4*)out;
#pragma unroll
        for (int v = 0; v < 2; v++) {
            int idx = (id * 256 + tid) * 2 + v;          // 0..65535
            int r = idx >> 7;
            int c = idx & 127;
            o4[r * 144 + c] = xin[idx];
        }
    }

    // Shared = NEGATED feat[:, k, :] packed as f32x2.
    for (int idx = tid; idx < NROWS * 4; idx += 256) {
        int j = idx >> 2;
        int c = (idx & 3) * 4;
        float4 v = *(const float4*)&g_feat[j * MM + k * DD + c];
        sNeg[j * 8 + (c >> 1) + 0] = pk2(-v.x, -v.y);
        sNeg[j * 8 + (c >> 1) + 1] = pk2(-v.z, -v.w);
    }
    __syncthreads();

    const int i = i0 + tid;

    unsigned long long fi[8];
    {
        const float4* p = (const float4*)&g_feat[i * MM + k * DD];
#pragma unroll
        for (int q = 0; q < 4; q++) {
            float4 v = p[q];
            fi[q * 2 + 0] = pk2(v.x, v.y);
            fi[q * 2 + 1] = pk2(v.z, v.w);
        }
    }

    const unsigned long long ABSM = 0x7fffffff7fffffffULL;
    float total0 = 0.f, total1 = 0.f;

#pragma unroll 2
    for (int j = 0; j < NROWS; j += 2) {
        const ulonglong2* rowA = (const ulonglong2*)&sNeg[j * 8];
        const ulonglong2* rowB = (const ulonglong2*)&sNeg[j * 8 + 8];
        ulonglong2 a0 = rowA[0], a1 = rowA[1], a2 = rowA[2], a3 = rowA[3];
        ulonglong2 b0 = rowB[0], b1 = rowB[1], b2 = rowB[2], b3 = rowB[3];

        // row j : tree reduction of 8 packed |diffs|
        unsigned long long dA[8];
        dA[0] = addf32x2(fi[0], a0.x) & ABSM;
        dA[1] = addf32x2(fi[1], a0.y) & ABSM;
        dA[2] = addf32x2(fi[2], a1.x) & ABSM;
        dA[3] = addf32x2(fi[3], a1.y) & ABSM;
        dA[4] = addf32x2(fi[4], a2.x) & ABSM;
        dA[5] = addf32x2(fi[5], a2.y) & ABSM;
        dA[6] = addf32x2(fi[6], a3.x) & ABSM;
        dA[7] = addf32x2(fi[7], a3.y) & ABSM;
        unsigned long long sA0 = addf32x2(addf32x2(dA[0], dA[1]),
                                          addf32x2(dA[2], dA[3]));
        unsigned long long sA1 = addf32x2(addf32x2(dA[4], dA[5]),
                                          addf32x2(dA[6], dA[7]));
        unsigned long long sA = addf32x2(sA0, sA1);
        float normA = lo32(sA) + hi32(sA);

        // row j+1
        unsigned long long dB[8];
        dB[0] = addf32x2(fi[0], b0.x) & ABSM;
        dB[1] = addf32x2(fi[1], b0.y) & ABSM;
        dB[2] = addf32x2(fi[2], b1.x) & ABSM;
        dB[3] = addf32x2(fi[3], b1.y) & ABSM;
        dB[4] = addf32x2(fi[4], b2.x) & ABSM;
        dB[5] = addf32x2(fi[5], b2.y) & ABSM;
        dB[6] = addf32x2(fi[6], b3.x) & ABSM;
        dB[7] = addf32x2(fi[7], b3.y) & ABSM;
        unsigned long long sB0 = addf32x2(addf32x2(dB[0], dB[1]),
                                          addf32x2(dB[2], dB[3]));
        unsigned long long sB1 = addf32x2(addf32x2(dB[4], dB[5]),
                                          addf32x2(dB[6], dB[7]));
        unsigned long long sB = addf32x2(sB0, sB1);
        float normB = lo32(sB) + hi32(sB);

        float eA = __expf(-normA);
        float eB = __expf(-normB);
        total0 += (j     == i) ? 0.f : eA;
        total1 += (j + 1 == i) ? 0.f : eB;
    }

    out[i * OUTW + INSIZE + k] = total0 + total1;
}

// ---------------------------------------------------------------------------
extern "C" void kernel_launch(void* const* d_in, const int* in_sizes, int n_in,
                              void* d_out, int out_size) {
    const float* x = (const float*)d_in[0];   // [512,512]
    const float* W = (const float*)d_in[1];   // [1024,512]
    const float* b = (const float*)d_in[2];   // [1024]
    float* out = (float*)d_out;               // [512,576]

    dim3 ggrid(MM / 64, NROWS / 64);          // (16, 8) = 128 blocks
    gemm_kernel<<<ggrid, 256>>>(x, W, b);

    dim3 pgrid(KK, NROWS / 256);              // (64, 2) = 128 blocks
    pairwise_kernel<<<pgrid, 256>>>(x, out);
}